// round 12
// baseline (speedup 1.0000x reference)
#include <cuda_runtime.h>
#include <cuda_bf16.h>
#include <stdint.h>

#define NODES 65536
#define DIM   256
#define NEXP  8
#define HDIM  1024
#define NCHUNK 128
#define CHW    64

// -------------------- device scratch --------------------
// GMEM holds exact SMEM images. Row swizzle: granule' = granule ^ (row & 7) (16B granules).
static __device__ __align__(1024) __nv_bfloat16 g_Hsw [(size_t)NODES * DIM];        // [n][256 swz], 512B rows
static __device__ __align__(1024) __nv_bfloat16 g_W1sw[(size_t)NEXP * HDIM * DIM];  // chunk = 64 n-rows x 512B (32KB)
static __device__ __align__(1024) __nv_bfloat16 g_W2sw[(size_t)NEXP * HDIM * DIM];  // chunk = 256 n-rows x 128B (32KB)
static __device__ float g_gate[(size_t)NODES * NEXP];

// -------------------- asm helpers --------------------
__device__ __forceinline__ void mma16816(float c[4], const uint32_t a[4], const uint32_t b[2]) {
    asm volatile(
        "mma.sync.aligned.m16n8k16.row.col.f32.bf16.bf16.f32 "
        "{%0,%1,%2,%3}, {%4,%5,%6,%7}, {%8,%9}, {%0,%1,%2,%3};\n"
        : "+f"(c[0]), "+f"(c[1]), "+f"(c[2]), "+f"(c[3])
        : "r"(a[0]), "r"(a[1]), "r"(a[2]), "r"(a[3]), "r"(b[0]), "r"(b[1]));
}
__device__ __forceinline__ void ldm4(uint32_t r[4], uint32_t addr) {
    asm volatile("ldmatrix.sync.aligned.m8n8.x4.shared.b16 {%0,%1,%2,%3}, [%4];"
        : "=r"(r[0]), "=r"(r[1]), "=r"(r[2]), "=r"(r[3]) : "r"(addr));
}
__device__ __forceinline__ void mbar_init(uint32_t bar, uint32_t cnt) {
    asm volatile("mbarrier.init.shared.b64 [%0], %1;" :: "r"(bar), "r"(cnt) : "memory");
}
__device__ __forceinline__ void mbar_expect(uint32_t bar, uint32_t bytes) {
    asm volatile("mbarrier.arrive.expect_tx.shared.b64 _, [%0], %1;" :: "r"(bar), "r"(bytes) : "memory");
}
__device__ __forceinline__ void mbar_arrive(uint32_t bar) {
    asm volatile("mbarrier.arrive.shared.b64 _, [%0];" :: "r"(bar) : "memory");
}
__device__ __forceinline__ void bulk_g2s(uint32_t dst, const void* src, uint32_t bytes, uint32_t bar) {
    asm volatile("cp.async.bulk.shared::cta.global.mbarrier::complete_tx::bytes [%0], [%1], %2, [%3];"
        :: "r"(dst), "l"(src), "r"(bytes), "r"(bar) : "memory");
}
__device__ __forceinline__ void bar_wait(uint32_t bar, uint32_t ph) {
    asm volatile(
        "{\n\t.reg .pred P;\n"
        "LAB%=:\n\t"
        "mbarrier.try_wait.parity.acquire.cta.shared::cta.b64 P, [%0], %1, 0x989680;\n\t"
        "@!P bra LAB%=;\n\t}"
        :: "r"(bar), "r"(ph) : "memory");
}

// -------------------- prep kernels (validated in R9/R10 bench) --------------------
__global__ void k_cvt_H(const float* __restrict__ H) {
    size_t i = (size_t)blockIdx.x * 256 + threadIdx.x;
    int n7 = (int)((i >> 8) & 7);
    int d  = (int)(i & 255);
    int col = ((((d >> 3) ^ n7) << 3) | (d & 7));
    g_Hsw[(i & ~(size_t)255) + col] = __float2bfloat16(H[i]);
}
// W1 [e][d=256][h=1024] -> [e][h][d swz]; 64 h-rows per chunk contiguous
__global__ void k_cvt_W1(const float* __restrict__ W1) {
    __shared__ float t[32][33];
    int e = blockIdx.z, h0 = blockIdx.x * 32, d0 = blockIdx.y * 32;
    int tx = threadIdx.x, ty = threadIdx.y;
#pragma unroll
    for (int j = 0; j < 4; ++j) {
        int d = d0 + ty + j * 8;
        t[ty + j * 8][tx] = W1[((size_t)e * 256 + d) * 1024 + h0 + tx];
    }
    __syncthreads();
#pragma unroll
    for (int j = 0; j < 4; ++j) {
        int h = h0 + ty + j * 8, d = d0 + tx;
        int col = ((((d >> 3) ^ (h & 7)) << 3) | (d & 7));
        g_W1sw[((size_t)e * 1024 + h) * 256 + col] = __float2bfloat16(t[tx][ty + j * 8]);
    }
}
// W2 [e][h=1024][d=256] -> [e][c][d=256 rows][k=64 swz]
__global__ void k_cvt_W2(const float* __restrict__ W2) {
    __shared__ float t[32][33];
    int e = blockIdx.z, d0 = blockIdx.x * 32, h0 = blockIdx.y * 32;
    int tx = threadIdx.x, ty = threadIdx.y;
#pragma unroll
    for (int j = 0; j < 4; ++j) {
        int h = h0 + ty + j * 8;
        t[ty + j * 8][tx] = W2[((size_t)e * 1024 + h) * 256 + d0 + tx];
    }
    __syncthreads();
#pragma unroll
    for (int j = 0; j < 4; ++j) {
        int d = d0 + ty + j * 8, h = h0 + tx;
        int c = h >> 6, kk = h & 63;
        int col = ((((kk >> 3) ^ (d & 7)) << 3) | (kk & 7));
        g_W2sw[(((size_t)e * 16 + c) * 256 + d) * 64 + col] = __float2bfloat16(t[tx][ty + j * 8]);
    }
}
__global__ void k_gate(const float* __restrict__ H, const float* __restrict__ gw,
                       const float* __restrict__ gb) {
    __shared__ float gws[256 * 9];
    int tid = threadIdx.x, lane = tid & 31, wid = tid >> 5;
    for (int i = tid; i < 2048; i += 256) { int d = i >> 3, e = i & 7; gws[d * 9 + e] = gw[i]; }
    __syncthreads();
    size_t node = (size_t)blockIdx.x * 8 + wid;
    float acc[8];
#pragma unroll
    for (int e = 0; e < 8; ++e) acc[e] = 0.f;
#pragma unroll
    for (int i = 0; i < 8; ++i) {
        int d = lane + 32 * i;
        float hv = H[node * 256 + d];
#pragma unroll
        for (int e = 0; e < 8; ++e) acc[e] += hv * gws[d * 9 + e];
    }
#pragma unroll
    for (int off = 16; off > 0; off >>= 1)
#pragma unroll
        for (int e = 0; e < 8; ++e) acc[e] += __shfl_xor_sync(0xFFFFFFFFu, acc[e], off);
    float l[8];
#pragma unroll
    for (int e = 0; e < 8; ++e) l[e] = acc[e] + gb[e];
    float m = l[0];
#pragma unroll
    for (int e = 1; e < 8; ++e) m = fmaxf(m, l[e]);
    float ex[8], s = 0.f;
#pragma unroll
    for (int e = 0; e < 8; ++e) { ex[e] = expf(l[e] - m); s += ex[e]; }
    float inv = 1.f / s;
    if (lane < 8) {
        float v = 0.f;
#pragma unroll
        for (int e = 0; e < 8; ++e) if (lane == e) v = ex[e];
        g_gate[node * 8 + lane] = v * inv;
    }
}

// -------------------- main fused kernel --------------------
// 128 nodes/CTA, 288 threads. Warps 0-7 compute (16 rows each, full width), warp 8 = TMA.
// Per chunk: GEMM1 m16xn64 (f32 regs) -> in-register relu/bias/gate pack (D-frag == A-frag)
// -> GEMM2 m16xn256 accumulating y[16x256] in registers. No __syncthreads in the loop.
#define OFF_HS   0          // 65536
#define OFF_W1   65536      // 2 x 32768
#define OFF_W2   131072     // 2 x 32768
#define OFF_B1   196608     // 8192 bf16 = 16384 B (whole b1, staged once)
#define OFF_GATE 212992     // 128x8 f32 = 4096
#define OFF_STAT 217088     // 256 f32 = 1024
#define OFF_BAR  218112     // 9 mbarriers
#define SMEM_BYTES 218240
#define SXF 260
// bars: 0=Hs, 1+b=W1 full, 3+b=W2 full, 5+b=W1 free(cnt8), 7+b=W2 free(cnt8)
#define BARA(i) (smb + OFF_BAR + (i) * 8)

__global__ void __launch_bounds__(288, 1)
k_main(const float* __restrict__ H, const float* __restrict__ b1g,
       const float* __restrict__ b2g, const float* __restrict__ gamma,
       const float* __restrict__ beta, float* __restrict__ out)
{
    extern __shared__ char smem_raw[];
    const uint32_t smb = (uint32_t)__cvta_generic_to_shared(smem_raw);
    float* gate_s = reinterpret_cast<float*>(smem_raw + OFF_GATE);
    __nv_bfloat16* b1bf = reinterpret_cast<__nv_bfloat16*>(smem_raw + OFF_B1);

    const int tid = threadIdx.x;
    const int lane = tid & 31, wid = tid >> 5;
    const int lq = lane >> 2, lr = lane & 3;
    const int l16 = lane & 15;
    const uint32_t hi  = (uint32_t)(lane & 16);          // byte col offset for ldmatrix lane halves
    const uint32_t swz = (uint32_t)((l16 & 7) << 4);     // row swizzle (row&7)<<4
    const int node0 = blockIdx.x * 128;
    const int m0 = wid * 16;                             // rows for compute warps 0..7

    if (tid == 0) {
        for (int i = 0; i <= 4; ++i) mbar_init(BARA(i), 1);
        for (int i = 5; i <= 8; ++i) mbar_init(BARA(i), 8);
    }
    // stage gate + b1 (bf16)
    for (int i = tid; i < 128 * 8; i += 288) gate_s[i] = g_gate[(size_t)node0 * 8 + i];
    for (int i = tid; i < 8192; i += 288) b1bf[i] = __float2bfloat16(b1g[i]);
    __syncthreads();

    if (wid == 8) {
        // ================= TMA agent =================
        if (lane == 0) {
            mbar_expect(BARA(0), 65536);
            bulk_g2s(smb + OFF_HS, (const char*)(g_Hsw + (size_t)node0 * 256), 65536, BARA(0));
#pragma unroll
            for (int s = 0; s < 2; ++s) {
                mbar_expect(BARA(1 + s), 32768);
                bulk_g2s(smb + OFF_W1 + s * 32768, (const char*)(g_W1sw + (size_t)s * 16384), 32768, BARA(1 + s));
                mbar_expect(BARA(3 + s), 32768);
                bulk_g2s(smb + OFF_W2 + s * 32768, (const char*)(g_W2sw + (size_t)s * 16384), 32768, BARA(3 + s));
            }
        }
        for (int c = 0; c < NCHUNK - 2; ++c) {
            const int b = c & 1;
            const uint32_t ph = (uint32_t)((c >> 1) & 1);
            bar_wait(BARA(5 + b), ph);                 // all warps done GEMM1(c)
            if (lane == 0) {
                mbar_expect(BARA(1 + b), 32768);
                bulk_g2s(smb + OFF_W1 + b * 32768, (const char*)(g_W1sw + (size_t)(c + 2) * 16384), 32768, BARA(1 + b));
            }
            bar_wait(BARA(7 + b), ph);                 // all warps done GEMM2(c)
            if (lane == 0) {
                mbar_expect(BARA(3 + b), 32768);
                bulk_g2s(smb + OFF_W2 + b * 32768, (const char*)(g_W2sw + (size_t)(c + 2) * 16384), 32768, BARA(3 + b));
            }
        }
    } else {
        // ================= compute warps 0-7 =================
        float y[32][4];
#pragma unroll
        for (int g = 0; g < 32; ++g)
#pragma unroll
            for (int q = 0; q < 4; ++q) y[g][q] = 0.f;

        bar_wait(BARA(0), 0);                          // Hs resident
        const uint32_t paH = smb + OFF_HS + (uint32_t)(m0 + l16) * 512;
        const uint32_t pb1row = (uint32_t)l16 * 512;   // W1 row stride term
        const uint32_t pb2row = (uint32_t)l16 * 128;   // W2 row stride term

        for (int c = 0; c < NCHUNK; ++c) {
            const int b = c & 1;
            const uint32_t ph = (uint32_t)((c >> 1) & 1);

            // ---- GEMM1: a1[16 x 64] = Hs[m0..m0+15][0..255] @ W1chunk^T ----
            bar_wait(BARA(1 + b), ph);
            float a1[8][4];
#pragma unroll
            for (int t = 0; t < 8; ++t)
#pragma unroll
                for (int q = 0; q < 4; ++q) a1[t][q] = 0.f;
            const uint32_t pW1 = smb + OFF_W1 + (uint32_t)b * 32768 + pb1row;
#pragma unroll
            for (int kk = 0; kk < 16; ++kk) {
                const uint32_t co = ((uint32_t)(kk * 32) + hi) ^ swz;
                uint32_t A[4];
                ldm4(A, paH + co);
#pragma unroll
                for (int g = 0; g < 4; ++g) {
                    uint32_t bb[4];
                    ldm4(bb, pW1 + (uint32_t)(g * 8192) + co);
                    uint32_t bt0[2] = { bb[0], bb[2] };
                    uint32_t bt1[2] = { bb[1], bb[3] };
                    mma16816(a1[2 * g],     A, bt0);
                    mma16816(a1[2 * g + 1], A, bt1);
                }
            }
            if (lane == 0) mbar_arrive(BARA(5 + b));   // W1 buf free

            // ---- in-register epilogue: +b1, relu, *gate -> A-frags for GEMM2 ----
            const int e = c >> 4;
            const float w0 = gate_s[(m0 + lq) * 8 + e];
            const float w1 = gate_s[(m0 + lq + 8) * 8 + e];
            uint32_t a2f[4][4];
#pragma unroll
            for (int t = 0; t < 8; ++t) {
                const __nv_bfloat162 bpair =
                    *reinterpret_cast<const __nv_bfloat162*>(b1bf + (c * 64 + 8 * t + 2 * lr));
                const float bb0 = __bfloat162float(bpair.x);
                const float bb1 = __bfloat162float(bpair.y);
                float v00 = fmaxf(a1[t][0] + bb0, 0.f) * w0;
                float v01 = fmaxf(a1[t][1] + bb1, 0.f) * w0;
                float v10 = fmaxf(a1[t][2] + bb0, 0.f) * w1;
                float v11 = fmaxf(a1[t][3] + bb1, 0.f) * w1;
                __nv_bfloat162 p0 = __floats2bfloat162_rn(v00, v01);
                __nv_bfloat162 p1 = __floats2bfloat162_rn(v10, v11);
                a2f[t >> 1][(t & 1) * 2]     = *reinterpret_cast<uint32_t*>(&p0);
                a2f[t >> 1][(t & 1) * 2 + 1] = *reinterpret_cast<uint32_t*>(&p1);
            }

            // ---- GEMM2: y[16 x 256] += h[16 x 64] @ W2chunk^T ----
            bar_wait(BARA(3 + b), ph);
            const uint32_t pW2 = smb + OFF_W2 + (uint32_t)b * 32768 + pb2row;
#pragma unroll
            for (int kk = 0; kk < 4; ++kk) {
                const uint32_t co = ((uint32_t)(kk * 32) + hi) ^ swz;
#pragma unroll
                for (int g = 0; g < 16; ++g) {
                    uint32_t bb[4];
                    ldm4(bb, pW2 + (uint32_t)(g * 2048) + co);
                    uint32_t bt0[2] = { bb[0], bb[2] };
                    uint32_t bt1[2] = { bb[1], bb[3] };
                    mma16816(y[2 * g],     a2f[kk], bt0);
                    mma16816(y[2 * g + 1], a2f[kk], bt1);
                }
            }
            if (lane == 0) mbar_arrive(BARA(7 + b));   // W2 buf free
        }

        // ================= final epilogue =================
        __syncthreads();   // paired below with warp 8
        // stage b2 (reuse b1 region as f32)
        float* b2s = reinterpret_cast<float*>(smem_raw + OFF_B1);
        for (int i = tid; i < 2048; i += 288) b2s[i] = b2g[i];
        __syncthreads();

        float* xS = reinterpret_cast<float*>(smem_raw);
        const int r0 = m0 + lq, r1 = r0 + 8;
        const float* gr0 = gate_s + r0 * 8;
        const float* gr1 = gate_s + r1 * 8;
        float s0 = 0.f, q0 = 0.f, s1 = 0.f, q1 = 0.f;
#pragma unroll
        for (int g = 0; g < 32; ++g) {
            const int col = 8 * g + 2 * lr;
            float bx00 = 0.f, bx01 = 0.f, bx10 = 0.f, bx11 = 0.f;
#pragma unroll
            for (int ee = 0; ee < 8; ++ee) {
                const float2 bb = *reinterpret_cast<const float2*>(&b2s[ee * 256 + col]);
                bx00 += gr0[ee] * bb.x; bx01 += gr0[ee] * bb.y;
                bx10 += gr1[ee] * bb.x; bx11 += gr1[ee] * bb.y;
            }
            float2 h0 = *reinterpret_cast<const float2*>(H + (size_t)(node0 + r0) * 256 + col);
            float2 h1 = *reinterpret_cast<const float2*>(H + (size_t)(node0 + r1) * 256 + col);
            float x00 = h0.x + y[g][0] + bx00, x01 = h0.y + y[g][1] + bx01;
            float x10 = h1.x + y[g][2] + bx10, x11 = h1.y + y[g][3] + bx11;
            xS[r0 * SXF + col] = x00; xS[r0 * SXF + col + 1] = x01;
            xS[r1 * SXF + col] = x10; xS[r1 * SXF + col + 1] = x11;
            s0 += x00 + x01; q0 += x00 * x00 + x01 * x01;
            s1 += x10 + x11; q1 += x10 * x10 + x11 * x11;
        }
        // quad reduce (lanes sharing lq: lane bits 0-1)
#pragma unroll
        for (int off = 1; off <= 2; off <<= 1) {
            s0 += __shfl_xor_sync(0xFFFFFFFFu, s0, off);
            q0 += __shfl_xor_sync(0xFFFFFFFFu, q0, off);
            s1 += __shfl_xor_sync(0xFFFFFFFFu, s1, off);
            q1 += __shfl_xor_sync(0xFFFFFFFFu, q1, off);
        }
        if (lr == 0) {
            float* stat = reinterpret_cast<float*>(smem_raw + OFF_STAT);
            float mu0 = s0 * (1.f / 256.f);
            float mu1 = s1 * (1.f / 256.f);
            stat[r0] = mu0; stat[128 + r0] = rsqrtf(q0 * (1.f / 256.f) - mu0 * mu0 + 1e-5f);
            stat[r1] = mu1; stat[128 + r1] = rsqrtf(q1 * (1.f / 256.f) - mu1 * mu1 + 1e-5f);
        }
    }
    if (wid == 8) { __syncthreads(); __syncthreads(); }   // pair with compute warps' two syncs
    __syncthreads();

    // ---- coalesced output ----
    {
        float* xS = reinterpret_cast<float*>(smem_raw);
        float* stat = reinterpret_cast<float*>(smem_raw + OFF_STAT);
        for (int idx4 = tid; idx4 < 8192; idx4 += 288) {
            int row = idx4 >> 6;
            int c4 = (idx4 & 63) * 4;
            float4 x = *reinterpret_cast<const float4*>(&xS[row * SXF + c4]);
            float mu = stat[row], rs = stat[128 + row];
            float4 g = *reinterpret_cast<const float4*>(gamma + c4);
            float4 bt = *reinterpret_cast<const float4*>(beta + c4);
            float4 o;
            o.x = (x.x - mu) * rs * g.x + bt.x;
            o.y = (x.y - mu) * rs * g.y + bt.y;
            o.z = (x.z - mu) * rs * g.z + bt.z;
            o.w = (x.w - mu) * rs * g.w + bt.w;
            *reinterpret_cast<float4*>(out + (size_t)(node0 + row) * 256 + c4) = o;
        }
    }
}

// -------------------- launch --------------------
extern "C" void kernel_launch(void* const* d_in, const int* in_sizes, int n_in,
                              void* d_out, int out_size) {
    (void)in_sizes; (void)n_in; (void)out_size;
    const float* H      = (const float*)d_in[0];
    const float* gate_w = (const float*)d_in[1];
    const float* gate_b = (const float*)d_in[2];
    const float* W1     = (const float*)d_in[3];
    const float* b1     = (const float*)d_in[4];
    const float* W2     = (const float*)d_in[5];
    const float* b2     = (const float*)d_in[6];
    const float* gamma  = (const float*)d_in[7];
    const float* beta   = (const float*)d_in[8];
    float* out = (float*)d_out;

    cudaFuncSetAttribute(k_main, cudaFuncAttributeMaxDynamicSharedMemorySize, SMEM_BYTES);

    k_cvt_H <<<NODES * DIM / 256, 256>>>(H);
    k_cvt_W1<<<dim3(32, 8, 8), dim3(32, 8)>>>(W1);
    k_cvt_W2<<<dim3(8, 32, 8), dim3(32, 8)>>>(W2);
    k_gate  <<<NODES / 8, 256>>>(H, gate_w, gate_b);
    k_main  <<<NODES / 128, 288, SMEM_BYTES>>>(H, b1, b2, gamma, beta, out);
}

// round 15
// speedup vs baseline: 1.4929x; 1.4929x over previous
#include <cuda_runtime.h>
#include <cuda_bf16.h>
#include <stdint.h>

#define NODES 65536
#define DIM   256
#define NEXP  8
#define HDIM  1024
#define NCHUNK 128
#define CHW    64

// -------------------- device scratch --------------------
// GMEM holds exact SMEM images. Row swizzle: 16B-granule' = granule ^ (row & 7).
static __device__ __align__(1024) __nv_bfloat16 g_Hsw [(size_t)NODES * DIM];        // [n][256 swz], 512B rows
static __device__ __align__(1024) __nv_bfloat16 g_W1sw[(size_t)NEXP * HDIM * DIM];  // chunk = 64 n-rows x 512B (32KB)
static __device__ __align__(1024) __nv_bfloat16 g_W2sw[(size_t)NEXP * HDIM * DIM];  // chunk = 256 n-rows x 128B (32KB)
static __device__ float g_gate[(size_t)NODES * NEXP];

// -------------------- asm helpers --------------------
__device__ __forceinline__ void mma16816(float c[4], const uint32_t a[4], const uint32_t b[2]) {
    asm volatile(
        "mma.sync.aligned.m16n8k16.row.col.f32.bf16.bf16.f32 "
        "{%0,%1,%2,%3}, {%4,%5,%6,%7}, {%8,%9}, {%0,%1,%2,%3};\n"
        : "+f"(c[0]), "+f"(c[1]), "+f"(c[2]), "+f"(c[3])
        : "r"(a[0]), "r"(a[1]), "r"(a[2]), "r"(a[3]), "r"(b[0]), "r"(b[1]));
}
__device__ __forceinline__ void ldm4(uint32_t r[4], uint32_t addr) {
    asm volatile("ldmatrix.sync.aligned.m8n8.x4.shared.b16 {%0,%1,%2,%3}, [%4];"
        : "=r"(r[0]), "=r"(r[1]), "=r"(r[2]), "=r"(r[3]) : "r"(addr));
}
__device__ __forceinline__ void mbar_init(uint32_t bar, uint32_t cnt) {
    asm volatile("mbarrier.init.shared.b64 [%0], %1;" :: "r"(bar), "r"(cnt) : "memory");
}
__device__ __forceinline__ void mbar_expect(uint32_t bar, uint32_t bytes) {
    asm volatile("mbarrier.arrive.expect_tx.shared.b64 _, [%0], %1;" :: "r"(bar), "r"(bytes) : "memory");
}
__device__ __forceinline__ void bulk_g2s(uint32_t dst, const void* src, uint32_t bytes, uint32_t bar) {
    asm volatile("cp.async.bulk.shared::cta.global.mbarrier::complete_tx::bytes [%0], [%1], %2, [%3];"
        :: "r"(dst), "l"(src), "r"(bytes), "r"(bar) : "memory");
}
__device__ __forceinline__ void bar_wait(uint32_t bar, uint32_t ph) {
    asm volatile(
        "{\n\t.reg .pred P;\n"
        "LAB%=:\n\t"
        "mbarrier.try_wait.parity.acquire.cta.shared::cta.b64 P, [%0], %1, 0x989680;\n\t"
        "@!P bra LAB%=;\n\t}"
        :: "r"(bar), "r"(ph) : "memory");
}

// -------------------- prep kernels (validated R9-R12) --------------------
__global__ void k_cvt_H(const float* __restrict__ H) {
    size_t i = (size_t)blockIdx.x * 256 + threadIdx.x;
    int n7 = (int)((i >> 8) & 7);
    int d  = (int)(i & 255);
    int col = ((((d >> 3) ^ n7) << 3) | (d & 7));
    g_Hsw[(i & ~(size_t)255) + col] = __float2bfloat16(H[i]);
}
__global__ void k_cvt_W1(const float* __restrict__ W1) {
    __shared__ float t[32][33];
    int e = blockIdx.z, h0 = blockIdx.x * 32, d0 = blockIdx.y * 32;
    int tx = threadIdx.x, ty = threadIdx.y;
#pragma unroll
    for (int j = 0; j < 4; ++j) {
        int d = d0 + ty + j * 8;
        t[ty + j * 8][tx] = W1[((size_t)e * 256 + d) * 1024 + h0 + tx];
    }
    __syncthreads();
#pragma unroll
    for (int j = 0; j < 4; ++j) {
        int h = h0 + ty + j * 8, d = d0 + tx;
        int col = ((((d >> 3) ^ (h & 7)) << 3) | (d & 7));
        g_W1sw[((size_t)e * 1024 + h) * 256 + col] = __float2bfloat16(t[tx][ty + j * 8]);
    }
}
__global__ void k_cvt_W2(const float* __restrict__ W2) {
    __shared__ float t[32][33];
    int e = blockIdx.z, d0 = blockIdx.x * 32, h0 = blockIdx.y * 32;
    int tx = threadIdx.x, ty = threadIdx.y;
#pragma unroll
    for (int j = 0; j < 4; ++j) {
        int h = h0 + ty + j * 8;
        t[ty + j * 8][tx] = W2[((size_t)e * 1024 + h) * 256 + d0 + tx];
    }
    __syncthreads();
#pragma unroll
    for (int j = 0; j < 4; ++j) {
        int d = d0 + ty + j * 8, h = h0 + tx;
        int c = h >> 6, kk = h & 63;
        int col = ((((kk >> 3) ^ (d & 7)) << 3) | (kk & 7));
        g_W2sw[(((size_t)e * 16 + c) * 256 + d) * 64 + col] = __float2bfloat16(t[tx][ty + j * 8]);
    }
}
__global__ void k_gate(const float* __restrict__ H, const float* __restrict__ gw,
                       const float* __restrict__ gb) {
    __shared__ float gws[256 * 9];
    int tid = threadIdx.x, lane = tid & 31, wid = tid >> 5;
    for (int i = tid; i < 2048; i += 256) { int d = i >> 3, e = i & 7; gws[d * 9 + e] = gw[i]; }
    __syncthreads();
    size_t node = (size_t)blockIdx.x * 8 + wid;
    float acc[8];
#pragma unroll
    for (int e = 0; e < 8; ++e) acc[e] = 0.f;
#pragma unroll
    for (int i = 0; i < 8; ++i) {
        int d = lane + 32 * i;
        float hv = H[node * 256 + d];
#pragma unroll
        for (int e = 0; e < 8; ++e) acc[e] += hv * gws[d * 9 + e];
    }
#pragma unroll
    for (int off = 16; off > 0; off >>= 1)
#pragma unroll
        for (int e = 0; e < 8; ++e) acc[e] += __shfl_xor_sync(0xFFFFFFFFu, acc[e], off);
    float l[8];
#pragma unroll
    for (int e = 0; e < 8; ++e) l[e] = acc[e] + gb[e];
    float m = l[0];
#pragma unroll
    for (int e = 1; e < 8; ++e) m = fmaxf(m, l[e]);
    float ex[8], s = 0.f;
#pragma unroll
    for (int e = 0; e < 8; ++e) { ex[e] = expf(l[e] - m); s += ex[e]; }
    float inv = 1.f / s;
    if (lane < 8) {
        float v = 0.f;
#pragma unroll
        for (int e = 0; e < 8; ++e) if (lane == e) v = ex[e];
        g_gate[node * 8 + lane] = v * inv;
    }
}

// -------------------- main fused kernel --------------------
// R9 datapaths verbatim; restructured pipeline:
//   ONE __syncthreads per chunk, hS double-buffered, W1 single-buffered,
//   W2 double-buffered. All TMA refills issued by tid 0 at the sync point.
// 128 nodes/CTA, 512 threads (16 warps: wm=wid&3 -> 32 rows, wn=wid>>2).
#define OFF_HS   0          // 65536
#define OFF_W1   65536      // 32768 (single)
#define OFF_W2   98304      // 2 x 32768
#define OFF_HSH  163840     // 2 x 18432 (128 rows x 144B each)
#define OFF_GATE 200704     // 4096
#define OFF_B2   204800     // 8192
#define OFF_B1   212992     // 512 (2 x 64 f32)
#define OFF_STAT 213504     // 1024
#define OFF_BAR  214528     // 4 mbarriers: 0=Hs, 1=W1full, 2/3=W2full(buf)
#define SMEM_BYTES 214592
#define SXF 260
#define BARA(i) (smb + OFF_BAR + (i) * 8)

__global__ void __launch_bounds__(512, 1)
k_main(const float* __restrict__ H, const float* __restrict__ b1g,
       const float* __restrict__ b2g, const float* __restrict__ gamma,
       const float* __restrict__ beta, float* __restrict__ out)
{
    extern __shared__ char smem_raw[];
    const uint32_t smb = (uint32_t)__cvta_generic_to_shared(smem_raw);
    float* gate_s = reinterpret_cast<float*>(smem_raw + OFF_GATE);
    float* b2s    = reinterpret_cast<float*>(smem_raw + OFF_B2);
    float* b1s    = reinterpret_cast<float*>(smem_raw + OFF_B1);
    __nv_bfloat16* hS = reinterpret_cast<__nv_bfloat16*>(smem_raw + OFF_HSH);

    const int tid  = threadIdx.x;
    const int lane = tid & 31, wid = tid >> 5;
    const int wm = wid & 3, wn = wid >> 2;
    const int m0 = wm * 32;
    const int lq = lane >> 2, lr = lane & 3;
    const int l16 = lane & 15;
    const uint32_t hi = (uint32_t)((lane >> 4) << 4);
    const int node0 = blockIdx.x * 128;

    if (tid == 0) {
#pragma unroll
        for (int i = 0; i < 4; ++i) mbar_init(BARA(i), 1);
    }
    __syncthreads();

    if (tid == 0) {
        mbar_expect(BARA(0), 65536);
        bulk_g2s(smb + OFF_HS, (const char*)(g_Hsw + (size_t)node0 * 256), 65536, BARA(0));
        mbar_expect(BARA(1), 32768);
        bulk_g2s(smb + OFF_W1, (const char*)g_W1sw, 32768, BARA(1));
#pragma unroll
        for (int s = 0; s < 2; ++s) {
            mbar_expect(BARA(2 + s), 32768);
            bulk_g2s(smb + OFF_W2 + s * 32768, (const char*)(g_W2sw + (size_t)s * 16384), 32768, BARA(2 + s));
        }
    }

    for (int i = tid; i < 128 * 8; i += 512) gate_s[i] = g_gate[(size_t)node0 * 8 + i];
    for (int i = tid; i < 8 * 256; i += 512) b2s[i] = b2g[i];
    if (tid < CHW) b1s[tid] = b1g[tid];
    __syncthreads();

    float y[2][8][4];
#pragma unroll
    for (int mi = 0; mi < 2; ++mi)
#pragma unroll
        for (int ni = 0; ni < 8; ++ni)
#pragma unroll
            for (int q = 0; q < 4; ++q) y[mi][ni][q] = 0.f;

    bar_wait(BARA(0), 0);

    // precomputed fragment addresses (R9 verbatim)
    const int rA = m0 + l16;
    const uint32_t swA  = (uint32_t)((rA & 7) << 4);
    const uint32_t paH0 = smb + OFF_HS + rA * 512;
    const uint32_t paH1 = paH0 + 16 * 512;
    const int rB1 = wn * 16 + l16;
    const uint32_t swB1 = (uint32_t)((rB1 & 7) << 4);
    const uint32_t pb1  = smb + OFF_W1 + rB1 * 512;        // W1 single buffer
    uint32_t pw2off[4], swB2[4];
#pragma unroll
    for (int p = 0; p < 4; ++p) {
        int r = wn * 64 + p * 16 + l16;
        pw2off[p] = (uint32_t)(r * 128);
        swB2[p] = (uint32_t)((r & 7) << 4);
    }

    for (int cc = 0; cc < NCHUNK; ++cc) {
        const int b = cc & 1;

        // b1 prefetch for next chunk (warps 14-15) — R9 verbatim
        if (tid >= 448 && cc + 1 < NCHUNK)
            b1s[((cc + 1) & 1) * CHW + (tid - 448)] = b1g[(cc + 1) * CHW + (tid - 448)];

        // ---------------- GEMM1: [128x64] = Hs[128x256] @ W1chunk^T ----------------
        bar_wait(BARA(1), (uint32_t)(cc & 1));             // W1(cc) resident (single buf)
        float a1[2][2][4];
#pragma unroll
        for (int mi = 0; mi < 2; ++mi)
#pragma unroll
            for (int ni = 0; ni < 2; ++ni)
#pragma unroll
                for (int q = 0; q < 4; ++q) a1[mi][ni][q] = 0.f;

#pragma unroll
        for (int kk = 0; kk < 16; ++kk) {
            const uint32_t co = (uint32_t)(kk * 32) + hi;
            uint32_t a0[4], a2[4], bb[4];
            ldm4(a0, paH0 + (co ^ swA));
            ldm4(a2, paH1 + (co ^ swA));
            ldm4(bb, pb1 + (co ^ swB1));
            uint32_t bt0[2] = { bb[0], bb[2] };
            uint32_t bt1[2] = { bb[1], bb[3] };
            mma16816(a1[0][0], a0, bt0);
            mma16816(a1[0][1], a0, bt1);
            mma16816(a1[1][0], a2, bt0);
            mma16816(a1[1][1], a2, bt1);
        }

        // ---- epilogue1: +b1, relu, *gate -> hS buf b (R9 stores, ping-pong base) ----
        const int e = cc >> 4;
        __nv_bfloat16* hSb = hS + b * 9216;                // 18432 B = 9216 bf16
#pragma unroll
        for (int mi = 0; mi < 2; ++mi) {
            const int r0 = m0 + mi * 16 + lq, r1 = r0 + 8;
            const float w0 = gate_s[r0 * 8 + e], w1 = gate_s[r1 * 8 + e];
#pragma unroll
            for (int ni = 0; ni < 2; ++ni) {
                const int cl = wn * 16 + ni * 8 + lr * 2;
                const float bb0 = b1s[b * CHW + cl], bb1 = b1s[b * CHW + cl + 1];
                float v00 = fmaxf(a1[mi][ni][0] + bb0, 0.f) * w0;
                float v01 = fmaxf(a1[mi][ni][1] + bb1, 0.f) * w0;
                float v10 = fmaxf(a1[mi][ni][2] + bb0, 0.f) * w1;
                float v11 = fmaxf(a1[mi][ni][3] + bb1, 0.f) * w1;
                *reinterpret_cast<__nv_bfloat162*>(hSb + r0 * 72 + cl) = __floats2bfloat162_rn(v00, v01);
                *reinterpret_cast<__nv_bfloat162*>(hSb + r1 * 72 + cl) = __floats2bfloat162_rn(v10, v11);
            }
        }

        __syncthreads();   // THE single per-chunk fence:
                           //  - hS(cc) visible to GEMM2 readers
                           //  - W1(cc) reads done -> refill W1(cc+1) safe
                           //  - GEMM2(cc-1) done  -> refill W2(cc+1) safe (same-parity buf)

        if (tid == 0 && cc + 1 < NCHUNK) {
            mbar_expect(BARA(1), 32768);
            bulk_g2s(smb + OFF_W1, (const char*)(g_W1sw + (size_t)(cc + 1) * 16384), 32768, BARA(1));
            if (cc >= 1) {
                const int nb = (cc + 1) & 1;
                mbar_expect(BARA(2 + nb), 32768);
                bulk_g2s(smb + OFF_W2 + nb * 32768, (const char*)(g_W2sw + (size_t)(cc + 1) * 16384), 32768, BARA(2 + nb));
            }
        }

        // ---------------- GEMM2: y[128x256] += hS buf b @ W2chunk^T ----------------
        bar_wait(BARA(2 + b), (uint32_t)((cc >> 1) & 1));
        const uint32_t pw2 = smb + OFF_W2 + (uint32_t)b * 32768;
        const uint32_t pah0 = smb + OFF_HSH + (uint32_t)b * 18432 + (uint32_t)rA * 144;
        const uint32_t pah1 = pah0 + 16 * 144;
#pragma unroll
        for (int kk = 0; kk < 4; ++kk) {
            const uint32_t co = (uint32_t)(kk * 32) + hi;
            uint32_t a0[4], a2[4];
            ldm4(a0, pah0 + co);
            ldm4(a2, pah1 + co);
#pragma unroll
            for (int p = 0; p < 4; ++p) {
                uint32_t bb[4];
                ldm4(bb, pw2 + pw2off[p] + (co ^ swB2[p]));
                uint32_t bt0[2] = { bb[0], bb[2] };
                uint32_t bt1[2] = { bb[1], bb[3] };
                mma16816(y[0][2 * p],     a0, bt0);
                mma16816(y[0][2 * p + 1], a0, bt1);
                mma16816(y[1][2 * p],     a2, bt0);
                mma16816(y[1][2 * p + 1], a2, bt1);
            }
        }
        // no second sync: hS double-buffer + next chunk's sync provide all ordering
    }

    // ---------------- final epilogue: residual + gated b2, then LayerNorm ----------------
    __syncthreads();   // all GEMM2(127) done; smem region 0 reusable as xS
    float* xS = reinterpret_cast<float*>(smem_raw);
#pragma unroll
    for (int mi = 0; mi < 2; ++mi) {
        const int r0 = m0 + mi * 16 + lq, r1 = r0 + 8;
#pragma unroll
        for (int ni = 0; ni < 8; ++ni) {
            const int c2 = wn * 64 + ni * 8 + lr * 2;
            float bx00 = 0.f, bx01 = 0.f, bx10 = 0.f, bx11 = 0.f;
#pragma unroll
            for (int ee = 0; ee < 8; ++ee) {
                const float w0 = gate_s[r0 * 8 + ee];
                const float w1 = gate_s[r1 * 8 + ee];
                const float2 bb = *reinterpret_cast<const float2*>(&b2s[ee * 256 + c2]);
                bx00 += w0 * bb.x; bx01 += w0 * bb.y;
                bx10 += w1 * bb.x; bx11 += w1 * bb.y;
            }
            float2 h0 = *reinterpret_cast<const float2*>(H + (size_t)(node0 + r0) * 256 + c2);
            float2 h1 = *reinterpret_cast<const float2*>(H + (size_t)(node0 + r1) * 256 + c2);
            xS[r0 * SXF + c2]     = h0.x + y[mi][ni][0] + bx00;
            xS[r0 * SXF + c2 + 1] = h0.y + y[mi][ni][1] + bx01;
            xS[r1 * SXF + c2]     = h1.x + y[mi][ni][2] + bx10;
            xS[r1 * SXF + c2 + 1] = h1.y + y[mi][ni][3] + bx11;
        }
    }
    __syncthreads();

    // LayerNorm: each of 16 warps handles 8 rows (R9 verbatim)
    {
        float* stat = reinterpret_cast<float*>(smem_raw + OFF_STAT);
#pragma unroll
        for (int rr = 0; rr < 8; ++rr) {
            const int r = wid * 8 + rr;
            float xv[8], s = 0.f, s2 = 0.f;
#pragma unroll
            for (int i = 0; i < 8; ++i) {
                xv[i] = xS[r * SXF + lane + 32 * i];
                s += xv[i]; s2 += xv[i] * xv[i];
            }
#pragma unroll
            for (int off = 16; off > 0; off >>= 1) {
                s  += __shfl_xor_sync(0xFFFFFFFFu, s,  off);
                s2 += __shfl_xor_sync(0xFFFFFFFFu, s2, off);
            }
            const float mu  = s * (1.f / 256.f);
            const float var = s2 * (1.f / 256.f) - mu * mu;
            const float rs  = rsqrtf(var + 1e-5f);
#pragma unroll
            for (int i = 0; i < 8; ++i) {
                const int col = lane + 32 * i;
                out[(size_t)(node0 + r) * 256 + col] = (xv[i] - mu) * rs * gamma[col] + beta[col];
            }
        }
    }
}

// -------------------- launch --------------------
extern "C" void kernel_launch(void* const* d_in, const int* in_sizes, int n_in,
                              void* d_out, int out_size) {
    (void)in_sizes; (void)n_in; (void)out_size;
    const float* H      = (const float*)d_in[0];
    const float* gate_w = (const float*)d_in[1];
    const float* gate_b = (const float*)d_in[2];
    const float* W1     = (const float*)d_in[3];
    const float* b1     = (const float*)d_in[4];
    const float* W2     = (const float*)d_in[5];
    const float* b2     = (const float*)d_in[6];
    const float* gamma  = (const float*)d_in[7];
    const float* beta   = (const float*)d_in[8];
    float* out = (float*)d_out;

    cudaFuncSetAttribute(k_main, cudaFuncAttributeMaxDynamicSharedMemorySize, SMEM_BYTES);

    k_cvt_H <<<NODES * DIM / 256, 256>>>(H);
    k_cvt_W1<<<dim3(32, 8, 8), dim3(32, 8)>>>(W1);
    k_cvt_W2<<<dim3(8, 32, 8), dim3(32, 8)>>>(W2);
    k_gate  <<<NODES / 8, 256>>>(H, gate_w, gate_b);
    k_main  <<<NODES / 128, 512, SMEM_BYTES>>>(H, b1, b2, gamma, beta, out);
}

// round 16
// speedup vs baseline: 1.5302x; 1.0250x over previous
#include <cuda_runtime.h>
#include <cuda_bf16.h>
#include <stdint.h>

#define NODES 65536
#define DIM   256
#define NEXP  8
#define HDIM  1024
#define NCHUNK 128
#define CHW    64

// -------------------- device scratch --------------------
// GMEM holds exact SMEM images. Row swizzle: 16B-granule' = granule ^ (row & 7).
static __device__ __align__(1024) __nv_bfloat16 g_Hsw [(size_t)NODES * DIM];        // [n][256 swz], 512B rows
static __device__ __align__(1024) __nv_bfloat16 g_W1sw[(size_t)NEXP * HDIM * DIM];  // chunk = 64 n-rows x 512B (32KB)
static __device__ __align__(1024) __nv_bfloat16 g_W2sw[(size_t)NEXP * HDIM * DIM];  // chunk = 256 n-rows x 128B (32KB)

// -------------------- asm helpers --------------------
__device__ __forceinline__ void mma16816(float c[4], const uint32_t a[4], const uint32_t b[2]) {
    asm volatile(
        "mma.sync.aligned.m16n8k16.row.col.f32.bf16.bf16.f32 "
        "{%0,%1,%2,%3}, {%4,%5,%6,%7}, {%8,%9}, {%0,%1,%2,%3};\n"
        : "+f"(c[0]), "+f"(c[1]), "+f"(c[2]), "+f"(c[3])
        : "r"(a[0]), "r"(a[1]), "r"(a[2]), "r"(a[3]), "r"(b[0]), "r"(b[1]));
}
__device__ __forceinline__ void ldm4(uint32_t r[4], uint32_t addr) {
    asm volatile("ldmatrix.sync.aligned.m8n8.x4.shared.b16 {%0,%1,%2,%3}, [%4];"
        : "=r"(r[0]), "=r"(r[1]), "=r"(r[2]), "=r"(r[3]) : "r"(addr));
}
__device__ __forceinline__ void mbar_init(uint32_t bar, uint32_t cnt) {
    asm volatile("mbarrier.init.shared.b64 [%0], %1;" :: "r"(bar), "r"(cnt) : "memory");
}
__device__ __forceinline__ void mbar_expect(uint32_t bar, uint32_t bytes) {
    asm volatile("mbarrier.arrive.expect_tx.shared.b64 _, [%0], %1;" :: "r"(bar), "r"(bytes) : "memory");
}
__device__ __forceinline__ void bulk_g2s(uint32_t dst, const void* src, uint32_t bytes, uint32_t bar) {
    asm volatile("cp.async.bulk.shared::cta.global.mbarrier::complete_tx::bytes [%0], [%1], %2, [%3];"
        :: "r"(dst), "l"(src), "r"(bytes), "r"(bar) : "memory");
}
__device__ __forceinline__ void bar_wait(uint32_t bar, uint32_t ph) {
    asm volatile(
        "{\n\t.reg .pred P;\n"
        "LAB%=:\n\t"
        "mbarrier.try_wait.parity.acquire.cta.shared::cta.b64 P, [%0], %1, 0x989680;\n\t"
        "@!P bra LAB%=;\n\t}"
        :: "r"(bar), "r"(ph) : "memory");
}

// -------------------- prep kernels (validated R9-R15) --------------------
__global__ void k_cvt_H(const float* __restrict__ H) {
    size_t i = (size_t)blockIdx.x * 256 + threadIdx.x;
    int n7 = (int)((i >> 8) & 7);
    int d  = (int)(i & 255);
    int col = ((((d >> 3) ^ n7) << 3) | (d & 7));
    g_Hsw[(i & ~(size_t)255) + col] = __float2bfloat16(H[i]);
}
__global__ void k_cvt_W1(const float* __restrict__ W1) {
    __shared__ float t[32][33];
    int e = blockIdx.z, h0 = blockIdx.x * 32, d0 = blockIdx.y * 32;
    int tx = threadIdx.x, ty = threadIdx.y;
#pragma unroll
    for (int j = 0; j < 4; ++j) {
        int d = d0 + ty + j * 8;
        t[ty + j * 8][tx] = W1[((size_t)e * 256 + d) * 1024 + h0 + tx];
    }
    __syncthreads();
#pragma unroll
    for (int j = 0; j < 4; ++j) {
        int h = h0 + ty + j * 8, d = d0 + tx;
        int col = ((((d >> 3) ^ (h & 7)) << 3) | (d & 7));
        g_W1sw[((size_t)e * 1024 + h) * 256 + col] = __float2bfloat16(t[tx][ty + j * 8]);
    }
}
__global__ void k_cvt_W2(const float* __restrict__ W2) {
    __shared__ float t[32][33];
    int e = blockIdx.z, d0 = blockIdx.x * 32, h0 = blockIdx.y * 32;
    int tx = threadIdx.x, ty = threadIdx.y;
#pragma unroll
    for (int j = 0; j < 4; ++j) {
        int h = h0 + ty + j * 8;
        t[ty + j * 8][tx] = W2[((size_t)e * 1024 + h) * 256 + d0 + tx];
    }
    __syncthreads();
#pragma unroll
    for (int j = 0; j < 4; ++j) {
        int d = d0 + ty + j * 8, h = h0 + tx;
        int c = h >> 6, kk = h & 63;
        int col = ((((kk >> 3) ^ (d & 7)) << 3) | (kk & 7));
        g_W2sw[(((size_t)e * 16 + c) * 256 + d) * 64 + col] = __float2bfloat16(t[tx][ty + j * 8]);
    }
}

// -------------------- main fused kernel --------------------
// R15 structure (1831us, passing) + gate fused into prologue + W2-wait hoist
// + 2-fragment GEMM2 kk0 B preload across the sync.
#define OFF_HS   0          // 65536
#define OFF_W1   65536      // 32768 (single)
#define OFF_W2   98304      // 2 x 32768
#define OFF_HSH  163840     // 2 x 18432 (gws overlays buf0 during prologue)
#define OFF_GATE 200704     // 4096
#define OFF_B2   204800     // 8192
#define OFF_B1   212992     // 512 (2 x 64 f32)
#define OFF_STAT 213504     // 1024
#define OFF_BAR  214528     // 4 mbarriers: 0=Hs, 1=W1full, 2/3=W2full(buf)
#define SMEM_BYTES 214592
#define SXF 260
#define BARA(i) (smb + OFF_BAR + (i) * 8)

__global__ void __launch_bounds__(512, 1)
k_main(const float* __restrict__ H, const float* __restrict__ gw,
       const float* __restrict__ gb, const float* __restrict__ b1g,
       const float* __restrict__ b2g, const float* __restrict__ gamma,
       const float* __restrict__ beta, float* __restrict__ out)
{
    extern __shared__ char smem_raw[];
    const uint32_t smb = (uint32_t)__cvta_generic_to_shared(smem_raw);
    float* gate_s = reinterpret_cast<float*>(smem_raw + OFF_GATE);
    float* b2s    = reinterpret_cast<float*>(smem_raw + OFF_B2);
    float* b1s    = reinterpret_cast<float*>(smem_raw + OFF_B1);
    __nv_bfloat16* hS = reinterpret_cast<__nv_bfloat16*>(smem_raw + OFF_HSH);

    const int tid  = threadIdx.x;
    const int lane = tid & 31, wid = tid >> 5;
    const int wm = wid & 3, wn = wid >> 2;
    const int m0 = wm * 32;
    const int lq = lane >> 2, lr = lane & 3;
    const int l16 = lane & 15;
    const uint32_t hi = (uint32_t)((lane >> 4) << 4);
    const int node0 = blockIdx.x * 128;

    if (tid == 0) {
#pragma unroll
        for (int i = 0; i < 4; ++i) mbar_init(BARA(i), 1);
    }
    __syncthreads();

    if (tid == 0) {
        mbar_expect(BARA(0), 65536);
        bulk_g2s(smb + OFF_HS, (const char*)(g_Hsw + (size_t)node0 * 256), 65536, BARA(0));
        mbar_expect(BARA(1), 32768);
        bulk_g2s(smb + OFF_W1, (const char*)g_W1sw, 32768, BARA(1));
#pragma unroll
        for (int s = 0; s < 2; ++s) {
            mbar_expect(BARA(2 + s), 32768);
            bulk_g2s(smb + OFF_W2 + s * 32768, (const char*)(g_W2sw + (size_t)s * 16384), 32768, BARA(2 + s));
        }
    }

    // ---- prologue staging (overlaps TMA fills) ----
    {
        float* gws = reinterpret_cast<float*>(smem_raw + OFF_HSH);   // transient, dead before chunk 0
        for (int i = tid; i < 2048; i += 512) { int d = i >> 3, e = i & 7; gws[d * 9 + e] = gw[i]; }
        for (int i = tid; i < 8 * 256; i += 512) b2s[i] = b2g[i];
        if (tid < CHW) b1s[tid] = b1g[tid];
        __syncthreads();

        // ---- fused gate: warp w computes nodes w*8 .. w*8+7 (k_gate math verbatim) ----
        for (int r = 0; r < 8; ++r) {
            const int lrow = wid * 8 + r;
            const size_t node = (size_t)(node0 + lrow);
            float acc[8];
#pragma unroll
            for (int e = 0; e < 8; ++e) acc[e] = 0.f;
#pragma unroll
            for (int i = 0; i < 8; ++i) {
                int d = lane + 32 * i;
                float hv = H[node * 256 + d];
#pragma unroll
                for (int e = 0; e < 8; ++e) acc[e] += hv * gws[d * 9 + e];
            }
#pragma unroll
            for (int off = 16; off > 0; off >>= 1)
#pragma unroll
                for (int e = 0; e < 8; ++e) acc[e] += __shfl_xor_sync(0xFFFFFFFFu, acc[e], off);
            float l[8];
#pragma unroll
            for (int e = 0; e < 8; ++e) l[e] = acc[e] + gb[e];
            float m = l[0];
#pragma unroll
            for (int e = 1; e < 8; ++e) m = fmaxf(m, l[e]);
            float ex[8], s = 0.f;
#pragma unroll
            for (int e = 0; e < 8; ++e) { ex[e] = expf(l[e] - m); s += ex[e]; }
            float inv = 1.f / s;
            if (lane < 8) {
                float v = 0.f;
#pragma unroll
                for (int e = 0; e < 8; ++e) if (lane == e) v = ex[e];
                gate_s[lrow * 8 + lane] = v * inv;
            }
        }
        __syncthreads();   // gate_s visible; gws region (hS buf0) free for chunk 0
    }

    float y[2][8][4];
#pragma unroll
    for (int mi = 0; mi < 2; ++mi)
#pragma unroll
        for (int ni = 0; ni < 8; ++ni)
#pragma unroll
            for (int q = 0; q < 4; ++q) y[mi][ni][q] = 0.f;

    bar_wait(BARA(0), 0);

    // precomputed fragment addresses (R15 verbatim)
    const int rA = m0 + l16;
    const uint32_t swA  = (uint32_t)((rA & 7) << 4);
    const uint32_t paH0 = smb + OFF_HS + rA * 512;
    const uint32_t paH1 = paH0 + 16 * 512;
    const int rB1 = wn * 16 + l16;
    const uint32_t swB1 = (uint32_t)((rB1 & 7) << 4);
    const uint32_t pb1  = smb + OFF_W1 + rB1 * 512;        // W1 single buffer
    uint32_t pw2off[4], swB2[4];
#pragma unroll
    for (int p = 0; p < 4; ++p) {
        int r = wn * 64 + p * 16 + l16;
        pw2off[p] = (uint32_t)(r * 128);
        swB2[p] = (uint32_t)((r & 7) << 4);
    }

    for (int cc = 0; cc < NCHUNK; ++cc) {
        const int b = cc & 1;

        // b1 prefetch for next chunk (warps 14-15)
        if (tid >= 448 && cc + 1 < NCHUNK)
            b1s[((cc + 1) & 1) * CHW + (tid - 448)] = b1g[(cc + 1) * CHW + (tid - 448)];

        // ---------------- GEMM1: [128x64] = Hs[128x256] @ W1chunk^T ----------------
        bar_wait(BARA(1), (uint32_t)(cc & 1));             // W1(cc) resident (single buf)
        float a1[2][2][4];
#pragma unroll
        for (int mi = 0; mi < 2; ++mi)
#pragma unroll
            for (int ni = 0; ni < 2; ++ni)
#pragma unroll
                for (int q = 0; q < 4; ++q) a1[mi][ni][q] = 0.f;

#pragma unroll
        for (int kk = 0; kk < 16; ++kk) {
            const uint32_t co = (uint32_t)(kk * 32) + hi;
            uint32_t a0[4], a2[4], bb[4];
            ldm4(a0, paH0 + (co ^ swA));
            ldm4(a2, paH1 + (co ^ swA));
            ldm4(bb, pb1 + (co ^ swB1));
            uint32_t bt0[2] = { bb[0], bb[2] };
            uint32_t bt1[2] = { bb[1], bb[3] };
            mma16816(a1[0][0], a0, bt0);
            mma16816(a1[0][1], a0, bt1);
            mma16816(a1[1][0], a2, bt0);
            mma16816(a1[1][1], a2, bt1);
        }

        // ---- hoisted W2(cc) wait + partial kk0 B-frag preload (no hS dependency) ----
        bar_wait(BARA(2 + b), (uint32_t)((cc >> 1) & 1));
        const uint32_t pw2 = smb + OFF_W2 + (uint32_t)b * 32768;
        uint32_t pre0[4], pre1[4];
        ldm4(pre0, pw2 + pw2off[0] + (hi ^ swB2[0]));
        ldm4(pre1, pw2 + pw2off[1] + (hi ^ swB2[1]));

        // ---- epilogue1: +b1, relu, *gate -> hS buf b (R15 verbatim) ----
        const int e = cc >> 4;
        __nv_bfloat16* hSb = hS + b * 9216;
#pragma unroll
        for (int mi = 0; mi < 2; ++mi) {
            const int r0 = m0 + mi * 16 + lq, r1 = r0 + 8;
            const float w0 = gate_s[r0 * 8 + e], w1 = gate_s[r1 * 8 + e];
#pragma unroll
            for (int ni = 0; ni < 2; ++ni) {
                const int cl = wn * 16 + ni * 8 + lr * 2;
                const float bb0 = b1s[b * CHW + cl], bb1 = b1s[b * CHW + cl + 1];
                float v00 = fmaxf(a1[mi][ni][0] + bb0, 0.f) * w0;
                float v01 = fmaxf(a1[mi][ni][1] + bb1, 0.f) * w0;
                float v10 = fmaxf(a1[mi][ni][2] + bb0, 0.f) * w1;
                float v11 = fmaxf(a1[mi][ni][3] + bb1, 0.f) * w1;
                *reinterpret_cast<__nv_bfloat162*>(hSb + r0 * 72 + cl) = __floats2bfloat162_rn(v00, v01);
                *reinterpret_cast<__nv_bfloat162*>(hSb + r1 * 72 + cl) = __floats2bfloat162_rn(v10, v11);
            }
        }

        __syncthreads();   // single per-chunk fence (hS visible; W1/W2 refill-safe)

        if (tid == 0 && cc + 1 < NCHUNK) {
            mbar_expect(BARA(1), 32768);
            bulk_g2s(smb + OFF_W1, (const char*)(g_W1sw + (size_t)(cc + 1) * 16384), 32768, BARA(1));
            if (cc >= 1) {
                const int nb = (cc + 1) & 1;
                mbar_expect(BARA(2 + nb), 32768);
                bulk_g2s(smb + OFF_W2 + nb * 32768, (const char*)(g_W2sw + (size_t)(cc + 1) * 16384), 32768, BARA(2 + nb));
            }
        }

        // ---------------- GEMM2: y[128x256] += hS buf b @ W2chunk^T ----------------
        const uint32_t pah0 = smb + OFF_HSH + (uint32_t)b * 18432 + (uint32_t)rA * 144;
        const uint32_t pah1 = pah0 + 16 * 144;
#pragma unroll
        for (int kk = 0; kk < 4; ++kk) {
            const uint32_t co = (uint32_t)(kk * 32) + hi;
            uint32_t a0[4], a2[4];
            ldm4(a0, pah0 + co);
            ldm4(a2, pah1 + co);
#pragma unroll
            for (int p = 0; p < 4; ++p) {
                uint32_t bb[4];
                if (kk == 0 && p == 0) { bb[0] = pre0[0]; bb[1] = pre0[1]; bb[2] = pre0[2]; bb[3] = pre0[3]; }
                else if (kk == 0 && p == 1) { bb[0] = pre1[0]; bb[1] = pre1[1]; bb[2] = pre1[2]; bb[3] = pre1[3]; }
                else ldm4(bb, pw2 + pw2off[p] + (co ^ swB2[p]));
                uint32_t bt0[2] = { bb[0], bb[2] };
                uint32_t bt1[2] = { bb[1], bb[3] };
                mma16816(y[0][2 * p],     a0, bt0);
                mma16816(y[0][2 * p + 1], a0, bt1);
                mma16816(y[1][2 * p],     a2, bt0);
                mma16816(y[1][2 * p + 1], a2, bt1);
            }
        }
        // no second sync (R15-proven ping-pong ordering)
    }

    // ---------------- final epilogue: residual + gated b2, then LayerNorm ----------------
    __syncthreads();
    float* xS = reinterpret_cast<float*>(smem_raw);
#pragma unroll
    for (int mi = 0; mi < 2; ++mi) {
        const int r0 = m0 + mi * 16 + lq, r1 = r0 + 8;
#pragma unroll
        for (int ni = 0; ni < 8; ++ni) {
            const int c2 = wn * 64 + ni * 8 + lr * 2;
            float bx00 = 0.f, bx01 = 0.f, bx10 = 0.f, bx11 = 0.f;
#pragma unroll
            for (int ee = 0; ee < 8; ++ee) {
                const float w0 = gate_s[r0 * 8 + ee];
                const float w1 = gate_s[r1 * 8 + ee];
                const float2 bb = *reinterpret_cast<const float2*>(&b2s[ee * 256 + c2]);
                bx00 += w0 * bb.x; bx01 += w0 * bb.y;
                bx10 += w1 * bb.x; bx11 += w1 * bb.y;
            }
            float2 h0 = *reinterpret_cast<const float2*>(H + (size_t)(node0 + r0) * 256 + c2);
            float2 h1 = *reinterpret_cast<const float2*>(H + (size_t)(node0 + r1) * 256 + c2);
            xS[r0 * SXF + c2]     = h0.x + y[mi][ni][0] + bx00;
            xS[r0 * SXF + c2 + 1] = h0.y + y[mi][ni][1] + bx01;
            xS[r1 * SXF + c2]     = h1.x + y[mi][ni][2] + bx10;
            xS[r1 * SXF + c2 + 1] = h1.y + y[mi][ni][3] + bx11;
        }
    }
    __syncthreads();

    // LayerNorm: each of 16 warps handles 8 rows (R15 verbatim)
    {
#pragma unroll
        for (int rr = 0; rr < 8; ++rr) {
            const int r = wid * 8 + rr;
            float xv[8], s = 0.f, s2 = 0.f;
#pragma unroll
            for (int i = 0; i < 8; ++i) {
                xv[i] = xS[r * SXF + lane + 32 * i];
                s += xv[i]; s2 += xv[i] * xv[i];
            }
#pragma unroll
            for (int off = 16; off > 0; off >>= 1) {
                s  += __shfl_xor_sync(0xFFFFFFFFu, s,  off);
                s2 += __shfl_xor_sync(0xFFFFFFFFu, s2, off);
            }
            const float mu  = s * (1.f / 256.f);
            const float var = s2 * (1.f / 256.f) - mu * mu;
            const float rs  = rsqrtf(var + 1e-5f);
#pragma unroll
            for (int i = 0; i < 8; ++i) {
                const int col = lane + 32 * i;
                out[(size_t)(node0 + r) * 256 + col] = (xv[i] - mu) * rs * gamma[col] + beta[col];
            }
        }
    }
}

// -------------------- launch --------------------
extern "C" void kernel_launch(void* const* d_in, const int* in_sizes, int n_in,
                              void* d_out, int out_size) {
    (void)in_sizes; (void)n_in; (void)out_size;
    const float* H      = (const float*)d_in[0];
    const float* gate_w = (const float*)d_in[1];
    const float* gate_b = (const float*)d_in[2];
    const float* W1     = (const float*)d_in[3];
    const float* b1     = (const float*)d_in[4];
    const float* W2     = (const float*)d_in[5];
    const float* b2     = (const float*)d_in[6];
    const float* gamma  = (const float*)d_in[7];
    const float* beta   = (const float*)d_in[8];
    float* out = (float*)d_out;

    cudaFuncSetAttribute(k_main, cudaFuncAttributeMaxDynamicSharedMemorySize, SMEM_BYTES);

    k_cvt_H <<<NODES * DIM / 256, 256>>>(H);
    k_cvt_W1<<<dim3(32, 8, 8), dim3(32, 8)>>>(W1);
    k_cvt_W2<<<dim3(8, 32, 8), dim3(32, 8)>>>(W2);
    k_main  <<<NODES / 128, 512, SMEM_BYTES>>>(H, gate_w, gate_b, b1, b2, gamma, beta, out);
}